// round 4
// baseline (speedup 1.0000x reference)
#include <cuda_runtime.h>
#include <math.h>

#define NJ     23
#define NP     16
#define NPAIR  8
#define VTOT   500000
#define V3     1500000
#define OUT_JOFF (NP * V3)

struct Ptrs { const float* p[11]; };

// constant-memory lookup tables (dynamic-index safe, no stack arrays)
__constant__ int c_PAR[NJ] = {-1,0,1,1,3,4,5,4,7,4,9,1,11,12,13,12,15,12,17,0,19,0,21};
// slot index into pose-param pointer array per joint (-1 = unposed)
__constant__ int c_SLOT[NJ] = { 0,-1,-1, 1, 2, 3,-1, 4,-1, 5,-1, 6, 7, 8,-1, 9,-1,10,-1,-1,-1,-1,-1};
#define QU 0.7853981633974483f
#define HA 1.5707963267948966f
__constant__ float c_SC[NJ] = {QU,0,0,HA,HA,QU,0,QU,0,QU,0,HA,HA,QU,0,QU,0,QU,0,0,0,0,0};

// dynamic shared layout (59 KB > 48 KB static limit)
struct Smem {
    float2 sA[NJ * NPAIR * 12];   // 17664 B, pose-pair interleaved skin matrices
    float  sW[256 * NJ];          // 23552 B, this block's weight rows
    float  sG[NP * NJ * 12];      // 17664 B, prep scratch: [Gr(3x3)|Gt] per joint per pose
    float2 sSh[NPAIR * 3];        // 192 B
};
#define SMEM_BYTES ((int)sizeof(Smem))

union F2U { float2 f; unsigned long long u; };
__device__ __forceinline__ float2 ffma2(float2 a, float2 b, float2 c)
{
    F2U A, B, C, D;
    A.f = a; B.f = b; C.f = c;
    asm("fma.rn.f32x2 %0, %1, %2, %3;"
        : "=l"(D.u) : "l"(A.u), "l"(B.u), "l"(C.u));
    return D.f;
}

__global__ void __launch_bounds__(256, 2)
lbs_fused(const float* __restrict__ verts,
          const float* __restrict__ W,
          const float* __restrict__ joints,
          const float* __restrict__ disp,
          const float* __restrict__ rnd,
          Ptrs pp,
          float* __restrict__ out)
{
    extern __shared__ unsigned char smem_raw[];
    Smem* sm = (Smem*)smem_raw;

    const int tid  = threadIdx.x;
    const int base = blockIdx.x << 8;

    if (tid >= 32) {
        // ---- warps 1..7: stage weight tile (hides prep + global latency) ----
        const int nv  = min(256, VTOT - base);
        const int nf4 = (nv * NJ) >> 2;          // exact: nv*23 divisible by 4
        float4* d = (float4*)sm->sW;
        const float4* s = (const float4*)(W + (size_t)base * NJ);
        for (int i = tid - 32; i < nf4; i += 224) d[i] = s[i];
    } else if (tid < NP) {
        // ---- warp 0, lanes 0..15: full prep, one pose per lane ----
        // NO local arrays anywhere (local-pool growth would trip the alloc guard)
        const int p = tid;
        float* Gp = sm->sG + p * (NJ * 12);

        #pragma unroll 1
        for (int j = 0; j < NJ; j++) {
            // pose vector for this joint (0 if unposed)
            float rx = 0.f, ry = 0.f, rz = 0.f;
            const int s = c_SLOT[j];
            if (s >= 0) {
                const float* prm = pp.p[s] + p * 3;
                const float sc = c_SC[j];
                rx = sc * tanhf(prm[0]);
                ry = sc * tanhf(prm[1]);
                rz = sc * tanhf(prm[2]);
            }
            // Rodrigues
            const float ang = sqrtf(rx*rx + ry*ry + rz*rz + 1e-16f);
            const float ax = rx / ang, ay = ry / ang, az = rz / ang;
            const float sn = sinf(ang), cs = cosf(ang), t = 1.0f - cs;
            float R0 = 1.f - t*(ay*ay + az*az), R1 = -sn*az + t*ax*ay, R2 =  sn*ay + t*ax*az;
            float R3 =  sn*az + t*ax*ay, R4 = 1.f - t*(ax*ax + az*az), R5 = -sn*ax + t*ay*az;
            float R6 = -sn*ay + t*ax*az, R7 =  sn*ax + t*ay*az, R8 = 1.f - t*(ax*ax + ay*ay);

            if (j == 0) {
                Gp[0] = R0; Gp[1] = R1; Gp[2]  = R2; Gp[3]  = joints[0];
                Gp[4] = R3; Gp[5] = R4; Gp[6]  = R5; Gp[7]  = joints[1];
                Gp[8] = R6; Gp[9] = R7; Gp[10] = R8; Gp[11] = joints[2];
            } else {
                const int q = c_PAR[j];
                const float rel0 = joints[3*j+0] - joints[3*q+0];
                const float rel1 = joints[3*j+1] - joints[3*q+1];
                const float rel2 = joints[3*j+2] - joints[3*q+2];
                float* Gj = Gp + j * 12;
                const float* Gq = Gp + q * 12;
                #pragma unroll
                for (int a = 0; a < 3; a++) {
                    const float g0 = Gq[a*4+0], g1 = Gq[a*4+1], g2 = Gq[a*4+2], g3 = Gq[a*4+3];
                    Gj[a*4+0] = g0*R0 + g1*R3 + g2*R6;
                    Gj[a*4+1] = g0*R1 + g1*R4 + g2*R7;
                    Gj[a*4+2] = g0*R2 + g1*R5 + g2*R8;
                    Gj[a*4+3] = g0*rel0 + g1*rel1 + g2*rel2 + g3;
                }
            }
        }

        const float sh0 = rnd[p*3+0] + 3.0f * tanhf(disp[p*3+0]);
        const float sh1 = rnd[p*3+1] + 3.0f * tanhf(disp[p*3+1]);
        const float sh2 = rnd[p*3+2] + 3.0f * tanhf(disp[p*3+2]);

        if (blockIdx.x == 0) {
            #pragma unroll 1
            for (int j = 0; j < NJ; j++) {
                out[OUT_JOFF + (p*NJ + j)*3 + 0] = Gp[j*12 + 3]  + sh0;
                out[OUT_JOFF + (p*NJ + j)*3 + 1] = Gp[j*12 + 7]  + sh1;
                out[OUT_JOFF + (p*NJ + j)*3 + 2] = Gp[j*12 + 11] + sh2;
            }
        }

        // A = [Gr | Gt - Gr*j_orig], pose-pair interleaved into sA
        const int pair = p >> 1, lane = p & 1;
        #pragma unroll 1
        for (int j = 0; j < NJ; j++) {
            const float jx = joints[3*j], jy = joints[3*j+1], jz = joints[3*j+2];
            const float* Gj = Gp + j * 12;
            float* dst = (float*)&sm->sA[(j*NPAIR + pair)*12];
            #pragma unroll
            for (int a = 0; a < 3; a++) {
                const float g0 = Gj[a*4+0], g1 = Gj[a*4+1], g2 = Gj[a*4+2];
                const float At = Gj[a*4+3] - (g0*jx + g1*jy + g2*jz);
                dst[(a*4+0)*2 + lane] = g0;
                dst[(a*4+1)*2 + lane] = g1;
                dst[(a*4+2)*2 + lane] = g2;
                dst[(a*4+3)*2 + lane] = At;
            }
        }
        ((float*)&sm->sSh[pair*3+0])[lane] = sh0;
        ((float*)&sm->sSh[pair*3+1])[lane] = sh1;
        ((float*)&sm->sSh[pair*3+2])[lane] = sh2;
    }
    __syncthreads();

    // ---- main: thread = 2 pose-pairs (4 poses) x 4 vertices ----
    const int vid = tid & 63;
    const int pg  = tid >> 6;          // 0..3 -> pairs {2pg, 2pg+1}
    const int v0  = base + vid;        // vertices v0 + {0,64,128,192}

    float2 x[4], y[4], z[4];
    #pragma unroll
    for (int u = 0; u < 4; u++) {
        int v = v0 + 64*u; if (v >= VTOT) v = VTOT - 1;   // clamp; stores guarded
        const float a = __ldg(&verts[v*3+0]);
        const float b = __ldg(&verts[v*3+1]);
        const float c = __ldg(&verts[v*3+2]);
        x[u] = make_float2(a, a); y[u] = make_float2(b, b); z[u] = make_float2(c, c);
    }

    float2 acc[2][3][4];
    #pragma unroll
    for (int pr = 0; pr < 2; pr++)
        #pragma unroll
        for (int r = 0; r < 3; r++)
            #pragma unroll
            for (int u = 0; u < 4; u++)
                acc[pr][r][u] = make_float2(0.f, 0.f);

    const float* sWp = sm->sW + vid * NJ;

    #pragma unroll 1
    for (int j = 0; j < NJ; j++) {
        float2 w[4];
        #pragma unroll
        for (int u = 0; u < 4; u++) {
            const float ww = sWp[u * (64*NJ) + j];
            w[u] = make_float2(ww, ww);
        }
        const float4* Aj = (const float4*)(sm->sA + (j*NPAIR + 2*pg)*12);

        #pragma unroll
        for (int pr = 0; pr < 2; pr++) {
            const float4 q0 = Aj[pr*6+0], q1 = Aj[pr*6+1], q2 = Aj[pr*6+2];
            const float4 q3 = Aj[pr*6+3], q4 = Aj[pr*6+4], q5 = Aj[pr*6+5];
            const float2 m00 = make_float2(q0.x,q0.y), m01 = make_float2(q0.z,q0.w);
            const float2 m02 = make_float2(q1.x,q1.y), m03 = make_float2(q1.z,q1.w);
            const float2 m10 = make_float2(q2.x,q2.y), m11 = make_float2(q2.z,q2.w);
            const float2 m12 = make_float2(q3.x,q3.y), m13 = make_float2(q3.z,q3.w);
            const float2 m20 = make_float2(q4.x,q4.y), m21 = make_float2(q4.z,q4.w);
            const float2 m22 = make_float2(q5.x,q5.y), m23 = make_float2(q5.z,q5.w);

            #pragma unroll
            for (int u = 0; u < 4; u++) {
                float2 t;
                t = ffma2(m00, x[u], ffma2(m01, y[u], ffma2(m02, z[u], m03)));
                acc[pr][0][u] = ffma2(w[u], t, acc[pr][0][u]);
                t = ffma2(m10, x[u], ffma2(m11, y[u], ffma2(m12, z[u], m13)));
                acc[pr][1][u] = ffma2(w[u], t, acc[pr][1][u]);
                t = ffma2(m20, x[u], ffma2(m21, y[u], ffma2(m22, z[u], m23)));
                acc[pr][2][u] = ffma2(w[u], t, acc[pr][2][u]);
            }
        }
    }

    // epilogue: add shift, store (full-line coverage: lanes stride 12B)
    #pragma unroll
    for (int pr = 0; pr < 2; pr++) {
        const int pair = 2*pg + pr;
        const int p0 = 2*pair;
        #pragma unroll
        for (int a = 0; a < 3; a++) {
            const float2 s = sm->sSh[pair*3 + a];
            #pragma unroll
            for (int u = 0; u < 4; u++) {
                const int v = v0 + 64*u;
                if (v < VTOT) {
                    out[ p0   *V3 + v*3 + a] = acc[pr][a][u].x + s.x;
                    out[(p0+1)*V3 + v*3 + a] = acc[pr][a][u].y + s.y;
                }
            }
        }
    }
}

// ---------------------------------------------------------------------------
extern "C" void kernel_launch(void* const* d_in, const int* in_sizes, int n_in,
                              void* d_out, int out_size)
{
    const float* vertices = (const float*)d_in[0];
    const float* joints   = (const float*)d_in[1];
    const float* weights  = (const float*)d_in[2];
    const float* disp     = (const float*)d_in[3];
    const float* rnd      = (const float*)d_in[4];
    Ptrs pp;
    for (int i = 0; i < 11; i++) pp.p[i] = (const float*)d_in[5 + i];
    float* out = (float*)d_out;

    // idempotent, immediate API — safe under graph capture
    cudaFuncSetAttribute(lbs_fused, cudaFuncAttributeMaxDynamicSharedMemorySize, SMEM_BYTES);

    const int nblocks = (VTOT + 255) / 256;   // 1954
    lbs_fused<<<nblocks, 256, SMEM_BYTES>>>(vertices, weights, joints, disp, rnd, pp, out);
}

// round 6
// speedup vs baseline: 1.8547x; 1.8547x over previous
#include <cuda_runtime.h>
#include <math.h>

#define NJ     23
#define NP     16
#define NPAIR  8
#define VTOT   500000
#define V3     1500000
#define OUT_JOFF (NP * V3)

struct Ptrs { const float* p[11]; };

// Pose-pair-interleaved skinning matrices: g_A2[(j*8+pair)*12 + a*4+b]
//   .x = pose 2*pair, .y = pose 2*pair+1 ; b==3 is translation column.
__device__ float2 g_A2[NJ * NPAIR * 12];
__device__ float2 g_shift2[NPAIR * 3];

// ---------------------------------------------------------------------------
// Kernel 1: tiny prep, one block, 16 active lanes (one pose each).
// Joint loop FULLY UNROLLED with local compile-time tables so the kinematic
// chain stays in registers (no local-memory spills, no shared, no syncs).
// A-matrix and posed-joint outputs are stored inside the loop so dead chain
// values retire and the live register frontier stays small.
// ---------------------------------------------------------------------------
__global__ void lbs_prep(const float* __restrict__ joints,
                         const float* __restrict__ disp,
                         const float* __restrict__ rnd,
                         Ptrs pp, float* __restrict__ out)
{
    const int p = threadIdx.x;
    if (p >= NP) return;

    // compile-time tables (constant-folded under full unroll)
    const int PAR[NJ]  = {-1,0,1,1,3,4,5,4,7,4,9,1,11,12,13,12,15,12,17,0,19,0,21};
    const int SLOT[NJ] = { 0,-1,-1, 1, 2, 3,-1, 4,-1, 5,-1, 6, 7, 8,-1, 9,-1,10,-1,-1,-1,-1,-1};
    const float QUART = 0.7853981633974483f, HALFPI = 1.5707963267948966f;
    const float SC[NJ] = {QUART,0,0,HALFPI,HALFPI,QUART,0,QUART,0,QUART,0,
                          HALFPI,HALFPI,QUART,0,QUART,0,QUART,0,0,0,0,0};

    const float sh0 = rnd[p*3+0] + 3.0f * tanhf(disp[p*3+0]);
    const float sh1 = rnd[p*3+1] + 3.0f * tanhf(disp[p*3+1]);
    const float sh2 = rnd[p*3+2] + 3.0f * tanhf(disp[p*3+2]);

    const int pair = p >> 1, lane = p & 1;

    float Gr[NJ][9];   // register-resident after unroll (constant indices only)
    float Gt[NJ][3];

    #pragma unroll
    for (int j = 0; j < NJ; j++) {
        // pose vector (compile-time-known whether this joint is posed)
        float rx = 0.f, ry = 0.f, rz = 0.f;
        if (SLOT[j] >= 0) {
            const float* prm = pp.p[SLOT[j]] + p * 3;
            rx = SC[j] * tanhf(prm[0]);
            ry = SC[j] * tanhf(prm[1]);
            rz = SC[j] * tanhf(prm[2]);
        }
        // Rodrigues
        const float ang = sqrtf(rx*rx + ry*ry + rz*rz + 1e-16f);
        const float ax = rx / ang, ay = ry / ang, az = rz / ang;
        const float sn = sinf(ang), cs = cosf(ang), t = 1.0f - cs;
        const float R0 = 1.f - t*(ay*ay + az*az), R1 = -sn*az + t*ax*ay, R2 =  sn*ay + t*ax*az;
        const float R3 =  sn*az + t*ax*ay, R4 = 1.f - t*(ax*ax + az*az), R5 = -sn*ax + t*ay*az;
        const float R6 = -sn*ay + t*ax*az, R7 =  sn*ax + t*ay*az, R8 = 1.f - t*(ax*ax + ay*ay);

        if (j == 0) {
            Gr[0][0]=R0; Gr[0][1]=R1; Gr[0][2]=R2;
            Gr[0][3]=R3; Gr[0][4]=R4; Gr[0][5]=R5;
            Gr[0][6]=R6; Gr[0][7]=R7; Gr[0][8]=R8;
            Gt[0][0]=joints[0]; Gt[0][1]=joints[1]; Gt[0][2]=joints[2];
        } else {
            const int q = PAR[j];                    // compile-time constant
            const float rel0 = joints[3*j+0] - joints[3*q+0];
            const float rel1 = joints[3*j+1] - joints[3*q+1];
            const float rel2 = joints[3*j+2] - joints[3*q+2];
            #pragma unroll
            for (int a = 0; a < 3; a++) {
                const float g0 = Gr[q][a*3+0], g1 = Gr[q][a*3+1], g2 = Gr[q][a*3+2];
                Gr[j][a*3+0] = g0*R0 + g1*R3 + g2*R6;
                Gr[j][a*3+1] = g0*R1 + g1*R4 + g2*R7;
                Gr[j][a*3+2] = g0*R2 + g1*R5 + g2*R8;
                Gt[j][a]     = g0*rel0 + g1*rel1 + g2*rel2 + Gt[q][a];
            }
        }

        // posed joints + shift
        out[OUT_JOFF + (p*NJ + j)*3 + 0] = Gt[j][0] + sh0;
        out[OUT_JOFF + (p*NJ + j)*3 + 1] = Gt[j][1] + sh1;
        out[OUT_JOFF + (p*NJ + j)*3 + 2] = Gt[j][2] + sh2;

        // A = [Gr | Gt - Gr*j_orig], pose-pair interleaved -> global
        const float jx = joints[3*j], jy = joints[3*j+1], jz = joints[3*j+2];
        float* dst = (float*)&g_A2[(j*NPAIR + pair)*12];
        #pragma unroll
        for (int a = 0; a < 3; a++) {
            const float g0 = Gr[j][a*3+0], g1 = Gr[j][a*3+1], g2 = Gr[j][a*3+2];
            const float At = Gt[j][a] - (g0*jx + g1*jy + g2*jz);
            dst[(a*4+0)*2 + lane] = g0;
            dst[(a*4+1)*2 + lane] = g1;
            dst[(a*4+2)*2 + lane] = g2;
            dst[(a*4+3)*2 + lane] = At;
        }
    }

    ((float*)&g_shift2[pair*3+0])[lane] = sh0;
    ((float*)&g_shift2[pair*3+1])[lane] = sh1;
    ((float*)&g_shift2[pair*3+2])[lane] = sh2;
}

// ---------------------------------------------------------------------------
// Packed f32x2 FMA (sm_103a FFMA2 — ptxas won't auto-fuse from C++)
// ---------------------------------------------------------------------------
union F2U { float2 f; unsigned long long u; };
__device__ __forceinline__ float2 ffma2(float2 a, float2 b, float2 c)
{
    F2U A, B, C, D;
    A.f = a; B.f = b; C.f = c;
    asm("fma.rn.f32x2 %0, %1, %2, %3;"
        : "=l"(D.u) : "l"(A.u), "l"(B.u), "l"(C.u));
    return D.f;
}

// ---------------------------------------------------------------------------
// Kernel 2: main. Block = 256 vertices x all 16 poses, 256 threads.
// Thread = 2 pose-pairs (4 poses) x 4 vertices -> FMA:LDS = 96:16 per j-iter.
// No forced min-blocks: ~108 regs + 41.4KB smem -> 2 blocks/SM naturally.
// ---------------------------------------------------------------------------
__global__ void __launch_bounds__(256)
lbs_main(const float* __restrict__ verts,
         const float* __restrict__ W,
         float* __restrict__ out)
{
    __shared__ __align__(16) float2 sA[NJ * NPAIR * 12];   // 17664 B
    __shared__ __align__(16) float  sW[256 * NJ];          // 23552 B
    __shared__ float2 sSh[NPAIR * 3];

    const int tid  = threadIdx.x;
    const int base = blockIdx.x << 8;

    // Stage A (broadcast matrix) via float4
    {
        float4* d = (float4*)sA;
        const float4* s = (const float4*)g_A2;
        for (int i = tid; i < (NJ * NPAIR * 12) / 2; i += 256) d[i] = s[i];
    }
    if (tid < NPAIR * 3) sSh[tid] = g_shift2[tid];

    // Stage this block's weight rows (nv*23 always divisible by 4)
    {
        const int nv  = min(256, VTOT - base);
        const int nf4 = (nv * NJ) >> 2;
        float4* d = (float4*)sW;
        const float4* s = (const float4*)(W + (size_t)base * NJ);
        for (int i = tid; i < nf4; i += 256) d[i] = s[i];
    }
    __syncthreads();

    const int vid = tid & 63;
    const int pg  = tid >> 6;          // 0..3 -> pose pairs {2pg, 2pg+1}
    const int v0  = base + vid;        // this thread: vertices v0 + {0,64,128,192}

    float2 x[4], y[4], z[4];
    #pragma unroll
    for (int u = 0; u < 4; u++) {
        int v = v0 + 64*u; if (v >= VTOT) v = VTOT - 1;   // clamp; stores guarded
        const float a = __ldg(&verts[v*3+0]);
        const float b = __ldg(&verts[v*3+1]);
        const float c = __ldg(&verts[v*3+2]);
        x[u] = make_float2(a, a); y[u] = make_float2(b, b); z[u] = make_float2(c, c);
    }

    float2 acc[2][3][4];
    #pragma unroll
    for (int pr = 0; pr < 2; pr++)
        #pragma unroll
        for (int r = 0; r < 3; r++)
            #pragma unroll
            for (int u = 0; u < 4; u++)
                acc[pr][r][u] = make_float2(0.f, 0.f);

    const float* sWp = sW + vid * NJ;

    #pragma unroll 1
    for (int j = 0; j < NJ; j++) {
        float2 w[4];
        #pragma unroll
        for (int u = 0; u < 4; u++) {
            const float ww = sWp[u * (64*NJ) + j];
            w[u] = make_float2(ww, ww);
        }
        const float4* Aj = (const float4*)(sA + (j*NPAIR + 2*pg)*12);

        #pragma unroll
        for (int pr = 0; pr < 2; pr++) {
            const float4 q0 = Aj[pr*6+0], q1 = Aj[pr*6+1], q2 = Aj[pr*6+2];
            const float4 q3 = Aj[pr*6+3], q4 = Aj[pr*6+4], q5 = Aj[pr*6+5];
            const float2 m00 = make_float2(q0.x,q0.y), m01 = make_float2(q0.z,q0.w);
            const float2 m02 = make_float2(q1.x,q1.y), m03 = make_float2(q1.z,q1.w);
            const float2 m10 = make_float2(q2.x,q2.y), m11 = make_float2(q2.z,q2.w);
            const float2 m12 = make_float2(q3.x,q3.y), m13 = make_float2(q3.z,q3.w);
            const float2 m20 = make_float2(q4.x,q4.y), m21 = make_float2(q4.z,q4.w);
            const float2 m22 = make_float2(q5.x,q5.y), m23 = make_float2(q5.z,q5.w);

            #pragma unroll
            for (int u = 0; u < 4; u++) {
                float2 t;
                t = ffma2(m00, x[u], ffma2(m01, y[u], ffma2(m02, z[u], m03)));
                acc[pr][0][u] = ffma2(w[u], t, acc[pr][0][u]);
                t = ffma2(m10, x[u], ffma2(m11, y[u], ffma2(m12, z[u], m13)));
                acc[pr][1][u] = ffma2(w[u], t, acc[pr][1][u]);
                t = ffma2(m20, x[u], ffma2(m21, y[u], ffma2(m22, z[u], m23)));
                acc[pr][2][u] = ffma2(w[u], t, acc[pr][2][u]);
            }
        }
    }

    // Epilogue: add shift, scatter to out[p][v][a]
    #pragma unroll
    for (int pr = 0; pr < 2; pr++) {
        const int pairc = 2*pg + pr;
        const int p0 = 2*pairc;
        #pragma unroll
        for (int a = 0; a < 3; a++) {
            const float2 s = sSh[pairc*3 + a];
            #pragma unroll
            for (int u = 0; u < 4; u++) {
                const int v = v0 + 64*u;
                if (v < VTOT) {
                    out[ p0   *V3 + v*3 + a] = acc[pr][a][u].x + s.x;
                    out[(p0+1)*V3 + v*3 + a] = acc[pr][a][u].y + s.y;
                }
            }
        }
    }
}

// ---------------------------------------------------------------------------
extern "C" void kernel_launch(void* const* d_in, const int* in_sizes, int n_in,
                              void* d_out, int out_size)
{
    const float* vertices = (const float*)d_in[0];
    const float* joints   = (const float*)d_in[1];
    const float* weights  = (const float*)d_in[2];
    const float* disp     = (const float*)d_in[3];
    const float* rnd      = (const float*)d_in[4];
    Ptrs pp;
    for (int i = 0; i < 11; i++) pp.p[i] = (const float*)d_in[5 + i];
    float* out = (float*)d_out;

    lbs_prep<<<1, 32>>>(joints, disp, rnd, pp, out);

    const int nblocks = (VTOT + 255) / 256;   // 1954
    lbs_main<<<nblocks, 256>>>(vertices, weights, out);
}